// round 6
// baseline (speedup 1.0000x reference)
#include <cuda_runtime.h>
#include <cuda_bf16.h>
#include <cstdint>

#define NFEAT 6272
#define MMEM  50000
#define CDIM  1024
#define BIMG  8
#define FHW   28
#define IMG   224
#define NPIX  (BIMG*IMG*IMG)

#define MTILE 128
#define NTILE 256
#define NTILES 196
#define MPAD2 (NTILES*NTILE)     // 50176
#define KCH   32                 // bf16 elems per K chunk
#define NCHUNKS (CDIM/KCH)       // 32
#define NSTAGE 3
#define NTHREADS 512

// smem: 80-byte padded rows (32 bf16 data + 8 pad) -> conflict-free ldmatrix
#define ROWB   80
#define ASTAGE (MTILE*ROWB)                  // 10240
#define BSTAGE (NTILE*ROWB)                  // 20480
#define SA_OFF(st) ((st)*ASTAGE)
#define SB_OFF(st) (NSTAGE*ASTAGE + (st)*BSTAGE)
#define AUX_OFF    (NSTAGE*(ASTAGE+BSTAGE))  // 92160
#define SMEM_TOTAL (AUX_OFF + 2048)          // m2s(256f) f2s(128f) sred(128u)

// ---- static device scratch ----
__device__ float g_f2[NFEAT];
__device__ float g_m2[MPAD2];
__device__ unsigned int g_minbits[NFEAT];
__device__ float g_gauss[17];
__device__ float g_resized[NPIX];
__device__ float g_tmpb[NPIX];
__device__ __nv_bfloat16 g_featb[NFEAT*CDIM];
__device__ __nv_bfloat16 g_memb[(size_t)MPAD2*CDIM];

static __device__ __forceinline__ uint32_t smem_u32(const void* p){
    uint32_t a; asm("{ .reg .u64 t; cvta.to.shared.u64 t, %1; cvt.u32.u64 %0, t; }"
                    : "=r"(a) : "l"(p));
    return a;
}
static __device__ __forceinline__ void cp16(uint32_t dst, const void* src){
    asm volatile("cp.async.cg.shared.global [%0], [%1], 16;" :: "r"(dst), "l"(src) : "memory");
}
static __device__ __forceinline__ void ldsm4(uint32_t p, uint32_t &r0, uint32_t &r1,
                                             uint32_t &r2, uint32_t &r3){
    asm volatile("ldmatrix.sync.aligned.m8n8.x4.shared.b16 {%0,%1,%2,%3}, [%4];"
                 : "=r"(r0), "=r"(r1), "=r"(r2), "=r"(r3) : "r"(p));
}
static __device__ __forceinline__ void mma16816(float* c, uint32_t a0, uint32_t a1,
                                                uint32_t a2, uint32_t a3,
                                                uint32_t b0, uint32_t b1){
    asm volatile("mma.sync.aligned.m16n8k16.row.col.f32.bf16.bf16.f32 "
                 "{%0,%1,%2,%3},{%4,%5,%6,%7},{%8,%9},{%0,%1,%2,%3};"
                 : "+f"(c[0]), "+f"(c[1]), "+f"(c[2]), "+f"(c[3])
                 : "r"(a0), "r"(a1), "r"(a2), "r"(a3), "r"(b0), "r"(b1));
}

// ---------------------------------------------------------------------------
__global__ void k_init(){
    int tid = blockIdx.x * blockDim.x + threadIdx.x;
    if (tid < NFEAT) g_minbits[tid] = 0x7F7FFFFFu;
    if (tid < 17){
        float s = 0.f;
        #pragma unroll
        for (int t = 0; t < 17; t++){ float d = (float)t - 8.f; s += expf(-(d*d)/32.f); }
        float d = (float)tid - 8.f;
        g_gauss[tid] = expf(-(d*d)/32.f) / s;
    }
}

// ---------------------------------------------------------------------------
// fused fp32->bf16 conversion + squared row norm. one warp per row.
// ---------------------------------------------------------------------------
__global__ void k_prep(const float* __restrict__ X, int nrows, int nvalid, int mode){
    int warp = (blockIdx.x * blockDim.x + threadIdx.x) >> 5;
    int lane = threadIdx.x & 31;
    if (warp >= nrows) return;
    __nv_bfloat16* dst = (mode == 0 ? g_featb : g_memb) + (size_t)warp * CDIM;
    if (warp >= nvalid){
        uint2 z = make_uint2(0u, 0u);
        #pragma unroll
        for (int j = 0; j < 8; j++) ((uint2*)dst)[j*32 + lane] = z;
        if (lane == 0) g_m2[warp] = __int_as_float(0x7F800000);
        return;
    }
    const float4* src = (const float4*)(X + (size_t)warp * CDIM);
    float s = 0.f;
    #pragma unroll
    for (int j = 0; j < 8; j++){
        float4 v = src[j*32 + lane];
        s += v.x*v.x + v.y*v.y + v.z*v.z + v.w*v.w;
        __nv_bfloat162 p0 = __floats2bfloat162_rn(v.x, v.y);
        __nv_bfloat162 p1 = __floats2bfloat162_rn(v.z, v.w);
        uint2 o; o.x = *(uint32_t*)&p0; o.y = *(uint32_t*)&p1;
        ((uint2*)dst)[j*32 + lane] = o;
    }
    #pragma unroll
    for (int o = 16; o > 0; o >>= 1) s += __shfl_xor_sync(0xFFFFFFFFu, s, o);
    if (lane == 0){ if (mode == 0) g_f2[warp] = s; else g_m2[warp] = s; }
}

// ---------------------------------------------------------------------------
// bf16 HMMA distance GEMM + min epilogue.
// CTA 128x256, 16 warps (2M x 8N), warp tile 64x32, 3-stage cp.async pipeline.
// ---------------------------------------------------------------------------
__global__ __launch_bounds__(NTHREADS, 2)
void k_gemm_tc(){
    extern __shared__ char smraw[];
    const uint32_t sbase = smem_u32(smraw);
    const int tid = threadIdx.x;
    const int wid = tid >> 5, lane = tid & 31;
    const int warpM = wid >> 3, warpN = wid & 7;
    const int rowBase = blockIdx.x * MTILE;
    const int colBase = blockIdx.y * NTILE;

    float* m2s = (float*)(smraw + AUX_OFF);
    float* f2s = (float*)(smraw + AUX_OFF + 1024);
    unsigned int* sred = (unsigned int*)(smraw + AUX_OFF + 1536);
    if (tid < NTILE) m2s[tid] = g_m2[colBase + tid];
    if (tid >= NTILE && tid < NTILE + MTILE) f2s[tid - NTILE] = g_f2[rowBase + tid - NTILE];
    if (tid >= NTILE + MTILE && tid < NTILE + 2*MTILE) sred[tid - NTILE - MTILE] = 0x7F7FFFFFu;

    const char* aG = (const char*)g_featb + (size_t)rowBase * (CDIM*2);
    const char* bG = (const char*)g_memb  + (size_t)colBase * (CDIM*2);

    // per-thread cp.async: t=0 -> A (512 x 16B), t=1,2 -> B (1024 x 16B)
    #define ISSUE_STAGE(ks, st) do { \
        { int row = tid >> 2, g = tid & 3; \
          cp16(sbase + SA_OFF(st) + row*ROWB + g*16, \
               aG + (size_t)row*(CDIM*2) + (ks)*(KCH*2) + g*16); } \
        _Pragma("unroll") \
        for (int t = 0; t < 2; t++){ \
            int j = tid + t*512; int row = j >> 2, g = j & 3; \
            cp16(sbase + SB_OFF(st) + row*ROWB + g*16, \
                 bG + (size_t)row*(CDIM*2) + (ks)*(KCH*2) + g*16); \
        } \
        asm volatile("cp.async.commit_group;" ::: "memory"); \
    } while(0)

    ISSUE_STAGE(0, 0);
    ISSUE_STAGE(1, 1);

    float acc[4][4][4];
    #pragma unroll
    for (int mi = 0; mi < 4; mi++)
        #pragma unroll
        for (int ni = 0; ni < 4; ni++)
            #pragma unroll
            for (int k = 0; k < 4; k++) acc[mi][ni][k] = 0.f;

    const int lrow = lane & 15;
    const int lcol16 = (lane >> 4) & 1;
    int stc = 0;   // current stage index

    for (int ks = 0; ks < NCHUNKS; ks++){
        asm volatile("cp.async.wait_group 1;" ::: "memory");
        __syncthreads();

        if (ks + 2 < NCHUNKS){
            int stn = stc + 2; if (stn >= NSTAGE) stn -= NSTAGE;
            ISSUE_STAGE(ks + 2, stn);
        } else {
            asm volatile("cp.async.commit_group;" ::: "memory");
        }

        const uint32_t sa = sbase + SA_OFF(stc);
        const uint32_t sb = sbase + SB_OFF(stc);

        #pragma unroll
        for (int k2 = 0; k2 < 2; k2++){
            uint32_t fa[4][4], fb[2][4];
            #pragma unroll
            for (int mi = 0; mi < 4; mi++){
                uint32_t p = sa + (warpM*64 + mi*16 + lrow)*ROWB + k2*32 + lcol16*16;
                ldsm4(p, fa[mi][0], fa[mi][1], fa[mi][2], fa[mi][3]);
            }
            #pragma unroll
            for (int nh = 0; nh < 2; nh++){
                uint32_t p = sb + (warpN*32 + nh*16 + lrow)*ROWB + k2*32 + lcol16*16;
                ldsm4(p, fb[nh][0], fb[nh][1], fb[nh][2], fb[nh][3]);
            }
            #pragma unroll
            for (int mi = 0; mi < 4; mi++)
                #pragma unroll
                for (int ni = 0; ni < 4; ni++){
                    int nh = ni >> 1, od = ni & 1;
                    mma16816(acc[mi][ni], fa[mi][0], fa[mi][1], fa[mi][2], fa[mi][3],
                             fb[nh][od], fb[nh][od + 2]);
                }
        }
        stc++; if (stc >= NSTAGE) stc -= NSTAGE;
    }
    #undef ISSUE_STAGE

    // ---- epilogue: d2 = f2 + m2 - 2*dot, min-reduce ----
    {
        const int q = lane >> 2;        // row-in-8 group
        const int ql = lane & 3;        // col pair selector
        float m2v[4][2], f2lo[4], f2hi[4];
        #pragma unroll
        for (int ni = 0; ni < 4; ni++){
            int c = warpN*32 + ni*8 + 2*ql;
            m2v[ni][0] = m2s[c];
            m2v[ni][1] = m2s[c + 1];
        }
        #pragma unroll
        for (int mi = 0; mi < 4; mi++){
            f2lo[mi] = f2s[warpM*64 + mi*16 + q];
            f2hi[mi] = f2s[warpM*64 + mi*16 + q + 8];
        }
        #pragma unroll
        for (int mi = 0; mi < 4; mi++){
            float vlo = __int_as_float(0x7F800000);
            float vhi = vlo;
            #pragma unroll
            for (int ni = 0; ni < 4; ni++){
                vlo = fminf(vlo, fminf(fmaf(-2.f, acc[mi][ni][0], f2lo[mi] + m2v[ni][0]),
                                       fmaf(-2.f, acc[mi][ni][1], f2lo[mi] + m2v[ni][1])));
                vhi = fminf(vhi, fminf(fmaf(-2.f, acc[mi][ni][2], f2hi[mi] + m2v[ni][0]),
                                       fmaf(-2.f, acc[mi][ni][3], f2hi[mi] + m2v[ni][1])));
            }
            #pragma unroll
            for (int o = 1; o < 4; o <<= 1){
                vlo = fminf(vlo, __shfl_xor_sync(0xFFFFFFFFu, vlo, o));
                vhi = fminf(vhi, __shfl_xor_sync(0xFFFFFFFFu, vhi, o));
            }
            if (ql == 0){
                int r = warpM*64 + mi*16 + q;
                atomicMin(&sred[r],     __float_as_uint(fmaxf(vlo, 0.f)));
                atomicMin(&sred[r + 8], __float_as_uint(fmaxf(vhi, 0.f)));
            }
        }
    }
    __syncthreads();
    if (tid < MTILE)
        atomicMin(&g_minbits[rowBase + tid], sred[tid]);
}

// ---------------------------------------------------------------------------
__global__ void k_scores(float* __restrict__ out){
    __shared__ unsigned int red[256];
    const int b = blockIdx.x;
    unsigned int mb = 0u;
    for (int i = threadIdx.x; i < FHW*FHW; i += 256)
        mb = max(mb, g_minbits[b*FHW*FHW + i]);
    red[threadIdx.x] = mb; __syncthreads();
    for (int s = 128; s > 0; s >>= 1){
        if (threadIdx.x < s) red[threadIdx.x] = max(red[threadIdx.x], red[threadIdx.x + s]);
        __syncthreads();
    }
    if (threadIdx.x == 0) out[b] = sqrtf(__uint_as_float(red[0]));
}

__global__ void k_resize(){
    int idx = blockIdx.x * blockDim.x + threadIdx.x;
    if (idx >= NPIX) return;
    int x = idx % IMG, y = (idx / IMG) % IMG, b = idx / (IMG*IMG);
    float fy = y * 0.125f - 0.4375f;
    float fx = x * 0.125f - 0.4375f;
    float fy0 = floorf(fy), fx0 = floorf(fx);
    float wy = fy - fy0, wx = fx - fx0;
    int y0 = max((int)fy0, 0), y1 = min((int)fy0 + 1, FHW-1);
    int x0 = max((int)fx0, 0), x1 = min((int)fx0 + 1, FHW-1);
    const unsigned int* mb = g_minbits + b*FHW*FHW;
    float s00 = sqrtf(__uint_as_float(mb[y0*FHW + x0]));
    float s01 = sqrtf(__uint_as_float(mb[y0*FHW + x1]));
    float s10 = sqrtf(__uint_as_float(mb[y1*FHW + x0]));
    float s11 = sqrtf(__uint_as_float(mb[y1*FHW + x1]));
    g_resized[idx] = (1.f-wy)*((1.f-wx)*s00 + wx*s01) + wy*((1.f-wx)*s10 + wx*s11);
}

__global__ void k_blurh(){
    __shared__ float w[17];
    if (threadIdx.x < 17) w[threadIdx.x] = g_gauss[threadIdx.x];
    __syncthreads();
    int idx = blockIdx.x * blockDim.x + threadIdx.x;
    if (idx >= NPIX) return;
    int x = idx % IMG, y = (idx / IMG) % IMG, b = idx / (IMG*IMG);
    const float* img = g_resized + b*IMG*IMG;
    float s = 0.f;
    #pragma unroll
    for (int t = 0; t < 17; t++){
        int yy = y - 8 + t;
        yy = (yy < 0) ? -yy : yy;
        yy = (yy > IMG-1) ? 2*(IMG-1) - yy : yy;
        s += w[t] * img[yy*IMG + x];
    }
    g_tmpb[idx] = s;
}

__global__ void k_blurv(float* __restrict__ out){
    __shared__ float w[17];
    if (threadIdx.x < 17) w[threadIdx.x] = g_gauss[threadIdx.x];
    __syncthreads();
    int idx = blockIdx.x * blockDim.x + threadIdx.x;
    if (idx >= NPIX) return;
    int x = idx % IMG, y = (idx / IMG) % IMG, b = idx / (IMG*IMG);
    const float* img = g_tmpb + b*IMG*IMG;
    float s = 0.f;
    #pragma unroll
    for (int t = 0; t < 17; t++){
        int xx = x - 8 + t;
        xx = (xx < 0) ? -xx : xx;
        xx = (xx > IMG-1) ? 2*(IMG-1) - xx : xx;
        s += w[t] * img[y*IMG + xx];
    }
    out[BIMG + idx] = s;
}

// ---------------------------------------------------------------------------
extern "C" void kernel_launch(void* const* d_in, const int* in_sizes, int n_in,
                              void* d_out, int out_size){
    const float* feat = (const float*)d_in[0];
    const float* mem  = (const float*)d_in[1];
    if (n_in >= 2 && in_sizes[0] == MMEM * CDIM){
        const float* t = feat; feat = mem; mem = t;
    }
    float* out = (float*)d_out;

    cudaFuncSetAttribute(k_gemm_tc, cudaFuncAttributeMaxDynamicSharedMemorySize, SMEM_TOTAL);

    k_init<<<(NFEAT + 255)/256, 256>>>();
    k_prep<<<NFEAT/8, 256>>>(feat, NFEAT, NFEAT, 0);
    k_prep<<<MPAD2/8, 256>>>(mem, MPAD2, MMEM, 1);

    dim3 g(NFEAT/MTILE, NTILES);   // 49 x 196, x fastest -> B tile L2 reuse
    k_gemm_tc<<<g, NTHREADS, SMEM_TOTAL>>>();

    k_scores<<<BIMG, 256>>>(out);
    int pb = (NPIX + 255)/256;
    k_resize<<<pb, 256>>>();
    k_blurh<<<pb, 256>>>();
    k_blurv<<<pb, 256>>>(out);
}

// round 7
// speedup vs baseline: 5.1469x; 5.1469x over previous
#include <cuda_runtime.h>
#include <cuda_bf16.h>
#include <cstdint>

#define NFEAT 6272
#define MMEM  50000
#define CDIM  1024
#define BIMG  8
#define FHW   28
#define IMG   224
#define NPIX  (BIMG*IMG*IMG)

#define MTILE 128
#define NTILE 128
#define NTILES 391
#define MPAD2 (NTILES*NTILE)     // 50048
#define KCH   32                 // bf16 elems per K chunk
#define NCHUNKS (CDIM/KCH)       // 32
#define NSTAGE 4

// smem: 80-byte padded rows (32 bf16 data + 8 pad) -> conflict-free ldmatrix
#define ROWB   80
#define STAGEB (MTILE*ROWB)      // 10240 per operand
#define SA_OFF(st) ((st)*STAGEB)
#define SB_OFF(st) (NSTAGE*STAGEB + (st)*STAGEB)
#define AUX_OFF    (2*NSTAGE*STAGEB)        // 81920
#define SMEM_TOTAL (AUX_OFF + 512*3)        // m2s, f2s, sred

// ---- static device scratch ----
__device__ float g_f2[NFEAT];
__device__ float g_m2[MPAD2];
__device__ unsigned int g_minbits[NFEAT];
__device__ float g_gauss[17];
__device__ float g_resized[NPIX];
__device__ float g_tmpb[NPIX];
__device__ __nv_bfloat16 g_featb[NFEAT*CDIM];
__device__ __nv_bfloat16 g_memb[(size_t)MPAD2*CDIM];

static __device__ __forceinline__ uint32_t smem_u32(const void* p){
    uint32_t a; asm("{ .reg .u64 t; cvta.to.shared.u64 t, %1; cvt.u32.u64 %0, t; }"
                    : "=r"(a) : "l"(p));
    return a;
}
static __device__ __forceinline__ void cp16(uint32_t dst, const void* src){
    asm volatile("cp.async.cg.shared.global [%0], [%1], 16;" :: "r"(dst), "l"(src) : "memory");
}
static __device__ __forceinline__ void ldsm4(uint32_t p, uint32_t &r0, uint32_t &r1,
                                             uint32_t &r2, uint32_t &r3){
    asm volatile("ldmatrix.sync.aligned.m8n8.x4.shared.b16 {%0,%1,%2,%3}, [%4];"
                 : "=r"(r0), "=r"(r1), "=r"(r2), "=r"(r3) : "r"(p));
}
static __device__ __forceinline__ void mma16816(float* c, uint32_t a0, uint32_t a1,
                                                uint32_t a2, uint32_t a3,
                                                uint32_t b0, uint32_t b1){
    asm volatile("mma.sync.aligned.m16n8k16.row.col.f32.bf16.bf16.f32 "
                 "{%0,%1,%2,%3},{%4,%5,%6,%7},{%8,%9},{%0,%1,%2,%3};"
                 : "+f"(c[0]), "+f"(c[1]), "+f"(c[2]), "+f"(c[3])
                 : "r"(a0), "r"(a1), "r"(a2), "r"(a3), "r"(b0), "r"(b1));
}

// ---------------------------------------------------------------------------
__global__ void k_init(){
    int tid = blockIdx.x * blockDim.x + threadIdx.x;
    if (tid < NFEAT) g_minbits[tid] = 0x7F7FFFFFu;
    if (tid < 17){
        float s = 0.f;
        #pragma unroll
        for (int t = 0; t < 17; t++){ float d = (float)t - 8.f; s += expf(-(d*d)/32.f); }
        float d = (float)tid - 8.f;
        g_gauss[tid] = expf(-(d*d)/32.f) / s;
    }
}

// ---------------------------------------------------------------------------
// fused fp32->bf16 conversion + squared row norm. one warp per row.
// ---------------------------------------------------------------------------
__global__ void k_prep(const float* __restrict__ X, int nrows, int nvalid, int mode){
    int warp = (blockIdx.x * blockDim.x + threadIdx.x) >> 5;
    int lane = threadIdx.x & 31;
    if (warp >= nrows) return;
    __nv_bfloat16* dst = (mode == 0 ? g_featb : g_memb) + (size_t)warp * CDIM;
    if (warp >= nvalid){
        uint2 z = make_uint2(0u, 0u);
        #pragma unroll
        for (int j = 0; j < 8; j++) ((uint2*)dst)[j*32 + lane] = z;
        if (lane == 0) g_m2[warp] = __int_as_float(0x7F800000);
        return;
    }
    const float4* src = (const float4*)(X + (size_t)warp * CDIM);
    float s = 0.f;
    #pragma unroll
    for (int j = 0; j < 8; j++){
        float4 v = src[j*32 + lane];
        s += v.x*v.x + v.y*v.y + v.z*v.z + v.w*v.w;
        __nv_bfloat162 p0 = __floats2bfloat162_rn(v.x, v.y);
        __nv_bfloat162 p1 = __floats2bfloat162_rn(v.z, v.w);
        uint2 o; o.x = *(uint32_t*)&p0; o.y = *(uint32_t*)&p1;
        ((uint2*)dst)[j*32 + lane] = o;
    }
    #pragma unroll
    for (int o = 16; o > 0; o >>= 1) s += __shfl_xor_sync(0xFFFFFFFFu, s, o);
    if (lane == 0){ if (mode == 0) g_f2[warp] = s; else g_m2[warp] = s; }
}

// ---------------------------------------------------------------------------
// bf16 HMMA distance GEMM + min epilogue.
// CTA 128x128, 8 warps (2M x 4N), warp tile 64x32.
// 4-stage smem, chunk-PAIR pipeline: one wait+sync per 2 chunks (16 barriers).
// ---------------------------------------------------------------------------
__global__ __launch_bounds__(256, 2)
void k_gemm_tc(){
    extern __shared__ char smraw[];
    const uint32_t sbase = smem_u32(smraw);
    const int tid = threadIdx.x;
    const int wid = tid >> 5, lane = tid & 31;
    const int warpM = wid >> 2, warpN = wid & 3;
    const int rowBase = blockIdx.x * MTILE;
    const int colBase = blockIdx.y * NTILE;

    float* m2s = (float*)(smraw + AUX_OFF);
    float* f2s = (float*)(smraw + AUX_OFF + 512);
    unsigned int* sred = (unsigned int*)(smraw + AUX_OFF + 1024);
    if (tid < 128){
        m2s[tid] = g_m2[colBase + tid];
        f2s[tid] = g_f2[rowBase + tid];
        sred[tid] = 0x7F7FFFFFu;
    }

    const char* aG = (const char*)g_featb + (size_t)rowBase * (CDIM*2);
    const char* bG = (const char*)g_memb  + (size_t)colBase * (CDIM*2);

    // issue a PAIR of chunks (2q, 2q+1) into stages (2q)&3, (2q+1)&3.
    // 2048 x 16B per pair -> 8 cp16 per thread, one commit_group per pair.
    #define ISSUE_PAIR(q) do { \
        _Pragma("unroll") \
        for (int t = 0; t < 8; t++){ \
            int i = tid + t * 256; \
            int h = (i >> 10) & 1;          /* chunk within pair */ \
            int ks = 2*(q) + h; \
            int st = ks & 3; \
            int j = i & 1023; \
            int row = (j & 511) >> 2, g = j & 3; \
            if (j < 512){ \
                cp16(sbase + SA_OFF(st) + row*ROWB + g*16, \
                     aG + (size_t)row*(CDIM*2) + ks*(KCH*2) + g*16); \
            } else { \
                cp16(sbase + SB_OFF(st) + row*ROWB + g*16, \
                     bG + (size_t)row*(CDIM*2) + ks*(KCH*2) + g*16); \
            } \
        } \
        asm volatile("cp.async.commit_group;" ::: "memory"); \
    } while(0)

    // prologue: pair 0
    ISSUE_PAIR(0);

    float acc[4][4][4];
    #pragma unroll
    for (int mi = 0; mi < 4; mi++)
        #pragma unroll
        for (int ni = 0; ni < 4; ni++)
            #pragma unroll
            for (int k = 0; k < 4; k++) acc[mi][ni][k] = 0.f;

    const int lrow = lane & 15;
    const int lcol16 = (lane >> 4) & 1;

    for (int p = 0; p < NCHUNKS/2; p++){
        asm volatile("cp.async.wait_group 0;" ::: "memory");
        __syncthreads();
        if (p + 1 < NCHUNKS/2) ISSUE_PAIR(p + 1);   // overlaps with compute below

        #pragma unroll
        for (int h = 0; h < 2; h++){
            const int st = (2*p + h) & 3;
            const uint32_t sa = sbase + SA_OFF(st);
            const uint32_t sb = sbase + SB_OFF(st);
            #pragma unroll
            for (int k2 = 0; k2 < 2; k2++){
                uint32_t fa[4][4], fb[2][4];
                #pragma unroll
                for (int mi = 0; mi < 4; mi++){
                    uint32_t pp = sa + (warpM*64 + mi*16 + lrow)*ROWB + k2*32 + lcol16*16;
                    ldsm4(pp, fa[mi][0], fa[mi][1], fa[mi][2], fa[mi][3]);
                }
                #pragma unroll
                for (int nh = 0; nh < 2; nh++){
                    uint32_t pp = sb + (warpN*32 + nh*16 + lrow)*ROWB + k2*32 + lcol16*16;
                    ldsm4(pp, fb[nh][0], fb[nh][1], fb[nh][2], fb[nh][3]);
                }
                #pragma unroll
                for (int mi = 0; mi < 4; mi++)
                    #pragma unroll
                    for (int ni = 0; ni < 4; ni++){
                        int nh = ni >> 1, od = ni & 1;
                        mma16816(acc[mi][ni], fa[mi][0], fa[mi][1], fa[mi][2], fa[mi][3],
                                 fb[nh][od], fb[nh][od + 2]);
                    }
            }
        }
    }
    #undef ISSUE_PAIR

    // ---- epilogue: d2 = f2 + m2 - 2*dot, min-reduce ----
    {
        const int q = lane >> 2;        // row-in-8 group
        const int ql = lane & 3;        // col pair selector
        float m2v[4][2], f2lo[4], f2hi[4];
        #pragma unroll
        for (int ni = 0; ni < 4; ni++){
            int c = warpN*32 + ni*8 + 2*ql;
            m2v[ni][0] = m2s[c];
            m2v[ni][1] = m2s[c + 1];
        }
        #pragma unroll
        for (int mi = 0; mi < 4; mi++){
            f2lo[mi] = f2s[warpM*64 + mi*16 + q];
            f2hi[mi] = f2s[warpM*64 + mi*16 + q + 8];
        }
        #pragma unroll
        for (int mi = 0; mi < 4; mi++){
            float vlo = __int_as_float(0x7F800000);
            float vhi = vlo;
            #pragma unroll
            for (int ni = 0; ni < 4; ni++){
                vlo = fminf(vlo, fminf(fmaf(-2.f, acc[mi][ni][0], f2lo[mi] + m2v[ni][0]),
                                       fmaf(-2.f, acc[mi][ni][1], f2lo[mi] + m2v[ni][1])));
                vhi = fminf(vhi, fminf(fmaf(-2.f, acc[mi][ni][2], f2hi[mi] + m2v[ni][0]),
                                       fmaf(-2.f, acc[mi][ni][3], f2hi[mi] + m2v[ni][1])));
            }
            #pragma unroll
            for (int o = 1; o < 4; o <<= 1){
                vlo = fminf(vlo, __shfl_xor_sync(0xFFFFFFFFu, vlo, o));
                vhi = fminf(vhi, __shfl_xor_sync(0xFFFFFFFFu, vhi, o));
            }
            if (ql == 0){
                int r = warpM*64 + mi*16 + q;
                atomicMin(&sred[r],     __float_as_uint(fmaxf(vlo, 0.f)));
                atomicMin(&sred[r + 8], __float_as_uint(fmaxf(vhi, 0.f)));
            }
        }
    }
    __syncthreads();
    if (tid < 128)
        atomicMin(&g_minbits[rowBase + tid], sred[tid]);
}

// ---------------------------------------------------------------------------
__global__ void k_scores(float* __restrict__ out){
    __shared__ unsigned int red[256];
    const int b = blockIdx.x;
    unsigned int mb = 0u;
    for (int i = threadIdx.x; i < FHW*FHW; i += 256)
        mb = max(mb, g_minbits[b*FHW*FHW + i]);
    red[threadIdx.x] = mb; __syncthreads();
    for (int s = 128; s > 0; s >>= 1){
        if (threadIdx.x < s) red[threadIdx.x] = max(red[threadIdx.x], red[threadIdx.x + s]);
        __syncthreads();
    }
    if (threadIdx.x == 0) out[b] = sqrtf(__uint_as_float(red[0]));
}

__global__ void k_resize(){
    int idx = blockIdx.x * blockDim.x + threadIdx.x;
    if (idx >= NPIX) return;
    int x = idx % IMG, y = (idx / IMG) % IMG, b = idx / (IMG*IMG);
    float fy = y * 0.125f - 0.4375f;
    float fx = x * 0.125f - 0.4375f;
    float fy0 = floorf(fy), fx0 = floorf(fx);
    float wy = fy - fy0, wx = fx - fx0;
    int y0 = max((int)fy0, 0), y1 = min((int)fy0 + 1, FHW-1);
    int x0 = max((int)fx0, 0), x1 = min((int)fx0 + 1, FHW-1);
    const unsigned int* mb = g_minbits + b*FHW*FHW;
    float s00 = sqrtf(__uint_as_float(mb[y0*FHW + x0]));
    float s01 = sqrtf(__uint_as_float(mb[y0*FHW + x1]));
    float s10 = sqrtf(__uint_as_float(mb[y1*FHW + x0]));
    float s11 = sqrtf(__uint_as_float(mb[y1*FHW + x1]));
    g_resized[idx] = (1.f-wy)*((1.f-wx)*s00 + wx*s01) + wy*((1.f-wx)*s10 + wx*s11);
}

__global__ void k_blurh(){
    __shared__ float w[17];
    if (threadIdx.x < 17) w[threadIdx.x] = g_gauss[threadIdx.x];
    __syncthreads();
    int idx = blockIdx.x * blockDim.x + threadIdx.x;
    if (idx >= NPIX) return;
    int x = idx % IMG, y = (idx / IMG) % IMG, b = idx / (IMG*IMG);
    const float* img = g_resized + b*IMG*IMG;
    float s = 0.f;
    #pragma unroll
    for (int t = 0; t < 17; t++){
        int yy = y - 8 + t;
        yy = (yy < 0) ? -yy : yy;
        yy = (yy > IMG-1) ? 2*(IMG-1) - yy : yy;
        s += w[t] * img[yy*IMG + x];
    }
    g_tmpb[idx] = s;
}

__global__ void k_blurv(float* __restrict__ out){
    __shared__ float w[17];
    if (threadIdx.x < 17) w[threadIdx.x] = g_gauss[threadIdx.x];
    __syncthreads();
    int idx = blockIdx.x * blockDim.x + threadIdx.x;
    if (idx >= NPIX) return;
    int x = idx % IMG, y = (idx / IMG) % IMG, b = idx / (IMG*IMG);
    const float* img = g_tmpb + b*IMG*IMG;
    float s = 0.f;
    #pragma unroll
    for (int t = 0; t < 17; t++){
        int xx = x - 8 + t;
        xx = (xx < 0) ? -xx : xx;
        xx = (xx > IMG-1) ? 2*(IMG-1) - xx : xx;
        s += w[t] * img[y*IMG + xx];
    }
    out[BIMG + idx] = s;
}

// ---------------------------------------------------------------------------
extern "C" void kernel_launch(void* const* d_in, const int* in_sizes, int n_in,
                              void* d_out, int out_size){
    const float* feat = (const float*)d_in[0];
    const float* mem  = (const float*)d_in[1];
    if (n_in >= 2 && in_sizes[0] == MMEM * CDIM){
        const float* t = feat; feat = mem; mem = t;
    }
    float* out = (float*)d_out;

    cudaFuncSetAttribute(k_gemm_tc, cudaFuncAttributeMaxDynamicSharedMemorySize, SMEM_TOTAL);

    k_init<<<(NFEAT + 255)/256, 256>>>();
    k_prep<<<NFEAT/8, 256>>>(feat, NFEAT, NFEAT, 0);
    k_prep<<<MPAD2/8, 256>>>(mem, MPAD2, MMEM, 1);

    dim3 g(NFEAT/MTILE, NTILES);   // 49 x 391, x fastest -> B tile L2 reuse
    k_gemm_tc<<<g, 256, SMEM_TOTAL>>>();

    k_scores<<<BIMG, 256>>>(out);
    int pb = (NPIX + 255)/256;
    k_resize<<<pb, 256>>>();
    k_blurh<<<pb, 256>>>();
    k_blurv<<<pb, 256>>>(out);
}

// round 8
// speedup vs baseline: 6.1136x; 1.1878x over previous
#include <cuda_runtime.h>
#include <cuda_bf16.h>
#include <cstdint>

#define NFEAT 6272
#define MMEM  50000
#define CDIM  1024
#define BIMG  8
#define FHW   28
#define IMG   224
#define NPIX  (BIMG*IMG*IMG)

#define MTILE 128
#define NTILE 128
#define NTILES 391
#define MPAD2 (NTILES*NTILE)     // 50048
#define KCH   32                 // bf16 elems per K chunk
#define NCHUNKS (CDIM/KCH)       // 32
#define NSTAGE 4

// smem: 80-byte padded rows (32 bf16 data + 8 pad) -> conflict-free ldmatrix
#define ROWB   80
#define STAGEB (MTILE*ROWB)      // 10240 per operand
#define SA_OFF(st) ((st)*STAGEB)
#define SB_OFF(st) (NSTAGE*STAGEB + (st)*STAGEB)
#define AUX_OFF    (2*NSTAGE*STAGEB)        // 81920
#define SMEM_TOTAL (AUX_OFF + 512*3)        // m2s, f2s, sred

// ---- static device scratch ----
__device__ float g_f2[NFEAT];
__device__ float g_m2[MPAD2];
__device__ unsigned int g_minbits[NFEAT];
__device__ float g_gauss[17];
__device__ float g_resized[NPIX];
__device__ float g_tmpb[NPIX];
__device__ __nv_bfloat16 g_featb[NFEAT*CDIM];
__device__ __nv_bfloat16 g_memb[(size_t)MPAD2*CDIM];

static __device__ __forceinline__ uint32_t smem_u32(const void* p){
    uint32_t a; asm("{ .reg .u64 t; cvta.to.shared.u64 t, %1; cvt.u32.u64 %0, t; }"
                    : "=r"(a) : "l"(p));
    return a;
}
static __device__ __forceinline__ void cp16(uint32_t dst, const void* src){
    asm volatile("cp.async.cg.shared.global [%0], [%1], 16;" :: "r"(dst), "l"(src) : "memory");
}
static __device__ __forceinline__ void ldsm4(uint32_t p, uint32_t &r0, uint32_t &r1,
                                             uint32_t &r2, uint32_t &r3){
    asm volatile("ldmatrix.sync.aligned.m8n8.x4.shared.b16 {%0,%1,%2,%3}, [%4];"
                 : "=r"(r0), "=r"(r1), "=r"(r2), "=r"(r3) : "r"(p));
}
static __device__ __forceinline__ void mma16816(float* c, uint32_t a0, uint32_t a1,
                                                uint32_t a2, uint32_t a3,
                                                uint32_t b0, uint32_t b1){
    asm volatile("mma.sync.aligned.m16n8k16.row.col.f32.bf16.bf16.f32 "
                 "{%0,%1,%2,%3},{%4,%5,%6,%7},{%8,%9},{%0,%1,%2,%3};"
                 : "+f"(c[0]), "+f"(c[1]), "+f"(c[2]), "+f"(c[3])
                 : "r"(a0), "r"(a1), "r"(a2), "r"(a3), "r"(b0), "r"(b1));
}

// ---------------------------------------------------------------------------
__global__ void k_init(){
    int tid = blockIdx.x * blockDim.x + threadIdx.x;
    if (tid < NFEAT) g_minbits[tid] = 0x7F7FFFFFu;
    if (tid < 17){
        float s = 0.f;
        #pragma unroll
        for (int t = 0; t < 17; t++){ float d = (float)t - 8.f; s += expf(-(d*d)/32.f); }
        float d = (float)tid - 8.f;
        g_gauss[tid] = expf(-(d*d)/32.f) / s;
    }
}

// ---------------------------------------------------------------------------
// fused fp32->bf16 conversion + squared row norm. one warp per row.
// ---------------------------------------------------------------------------
__global__ void k_prep(const float* __restrict__ X, int nrows, int nvalid, int mode){
    int warp = (blockIdx.x * blockDim.x + threadIdx.x) >> 5;
    int lane = threadIdx.x & 31;
    if (warp >= nrows) return;
    __nv_bfloat16* dst = (mode == 0 ? g_featb : g_memb) + (size_t)warp * CDIM;
    if (warp >= nvalid){
        uint2 z = make_uint2(0u, 0u);
        #pragma unroll
        for (int j = 0; j < 8; j++) ((uint2*)dst)[j*32 + lane] = z;
        if (lane == 0) g_m2[warp] = __int_as_float(0x7F800000);
        return;
    }
    const float4* src = (const float4*)(X + (size_t)warp * CDIM);
    float s = 0.f;
    #pragma unroll
    for (int j = 0; j < 8; j++){
        float4 v = src[j*32 + lane];
        s += v.x*v.x + v.y*v.y + v.z*v.z + v.w*v.w;
        __nv_bfloat162 p0 = __floats2bfloat162_rn(v.x, v.y);
        __nv_bfloat162 p1 = __floats2bfloat162_rn(v.z, v.w);
        uint2 o; o.x = *(uint32_t*)&p0; o.y = *(uint32_t*)&p1;
        ((uint2*)dst)[j*32 + lane] = o;
    }
    #pragma unroll
    for (int o = 16; o > 0; o >>= 1) s += __shfl_xor_sync(0xFFFFFFFFu, s, o);
    if (lane == 0){ if (mode == 0) g_f2[warp] = s; else g_m2[warp] = s; }
}

// ---------------------------------------------------------------------------
// bf16 HMMA distance GEMM + min epilogue.
// CTA 128x128, 8 warps (2M x 4N), warp tile 64x32.
// 4-stage smem ring, wait_group 1 (chunk ks+1 resident during chunk ks),
// fragment double-buffer: LDSM of next k16 step overlaps 16 MMAs of current.
// ---------------------------------------------------------------------------
__global__ __launch_bounds__(256, 2)
void k_gemm_tc(){
    extern __shared__ char smraw[];
    const uint32_t sbase = smem_u32(smraw);
    const int tid = threadIdx.x;
    const int wid = tid >> 5, lane = tid & 31;
    const int warpM = wid >> 2, warpN = wid & 3;
    const int rowBase = blockIdx.x * MTILE;
    const int colBase = blockIdx.y * NTILE;

    float* m2s = (float*)(smraw + AUX_OFF);
    float* f2s = (float*)(smraw + AUX_OFF + 512);
    unsigned int* sred = (unsigned int*)(smraw + AUX_OFF + 1024);
    if (tid < 128){
        m2s[tid] = g_m2[colBase + tid];
        f2s[tid] = g_f2[rowBase + tid];
        sred[tid] = 0x7F7FFFFFu;
    }

    // ---- precomputed per-thread cp.async endpoints (rows r0, r0+64 of A and B) ----
    const int r0 = tid >> 2, gq = tid & 3;
    const char* aSrc0 = (const char*)g_featb + ((size_t)(rowBase + r0))*(CDIM*2) + gq*16;
    const char* aSrc1 = aSrc0 + (size_t)64*(CDIM*2);
    const char* bSrc0 = (const char*)g_memb  + ((size_t)(colBase + r0))*(CDIM*2) + gq*16;
    const char* bSrc1 = bSrc0 + (size_t)64*(CDIM*2);
    const uint32_t aDst0 = sbase + r0*ROWB + gq*16;
    const uint32_t aDst1 = aDst0 + 64*ROWB;
    const uint32_t bDst0 = aDst0 + NSTAGE*STAGEB;
    const uint32_t bDst1 = bDst0 + 64*ROWB;

    #define ISSUE(ks) do { \
        const uint32_t _so = (uint32_t)(((ks) & 3) * STAGEB); \
        const size_t _ko = (size_t)(ks) * (KCH*2); \
        cp16(aDst0 + _so, aSrc0 + _ko); \
        cp16(aDst1 + _so, aSrc1 + _ko); \
        cp16(bDst0 + _so, bSrc0 + _ko); \
        cp16(bDst1 + _so, bSrc1 + _ko); \
        asm volatile("cp.async.commit_group;" ::: "memory"); \
    } while(0)

    // ---- precomputed LDSM base offsets ----
    const int lrow = lane & 15;
    const int lcol16 = (lane >> 4) & 1;
    const uint32_t aOff = sbase + (warpM*64 + lrow)*ROWB + lcol16*16;
    const uint32_t bOff = sbase + NSTAGE*STAGEB + (warpN*32 + lrow)*ROWB + lcol16*16;

    uint32_t fa[2][4][4], fb[2][2][4];
    #define LOAD_FRAGS(buf, ap, bp) do { \
        _Pragma("unroll") \
        for (int mi = 0; mi < 4; mi++) \
            ldsm4((ap) + mi*(16*ROWB), fa[buf][mi][0], fa[buf][mi][1], \
                  fa[buf][mi][2], fa[buf][mi][3]); \
        _Pragma("unroll") \
        for (int nh = 0; nh < 2; nh++) \
            ldsm4((bp) + nh*(16*ROWB), fb[buf][nh][0], fb[buf][nh][1], \
                  fb[buf][nh][2], fb[buf][nh][3]); \
    } while(0)

    #define MMA_STEP(buf) do { \
        _Pragma("unroll") \
        for (int mi = 0; mi < 4; mi++) \
            _Pragma("unroll") \
            for (int ni = 0; ni < 4; ni++){ \
                int nh = ni >> 1, od = ni & 1; \
                mma16816(acc[mi][ni], fa[buf][mi][0], fa[buf][mi][1], \
                         fa[buf][mi][2], fa[buf][mi][3], \
                         fb[buf][nh][od], fb[buf][nh][od + 2]); \
            } \
    } while(0)

    float acc[4][4][4];
    #pragma unroll
    for (int mi = 0; mi < 4; mi++)
        #pragma unroll
        for (int ni = 0; ni < 4; ni++)
            #pragma unroll
            for (int k = 0; k < 4; k++) acc[mi][ni][k] = 0.f;

    // prologue: chunks 0,1,2 in flight; wait until 0 and 1 resident
    ISSUE(0); ISSUE(1); ISSUE(2);
    asm volatile("cp.async.wait_group 1;" ::: "memory");
    __syncthreads();

    // preload fragments for (chunk 0, k2=0) into buf 0
    LOAD_FRAGS(0, aOff, bOff);

    for (int ks = 0; ks < NCHUNKS; ks++){
        if (ks > 0){
            asm volatile("cp.async.wait_group 1;" ::: "memory");
            __syncthreads();
        }
        if (ks + 3 < NCHUNKS) ISSUE(ks + 3);

        const uint32_t stc = (uint32_t)((ks & 3) * STAGEB);
        // k2=0: prefetch (ks, k2=1) into buf1, compute buf0
        LOAD_FRAGS(1, aOff + stc + 32, bOff + stc + 32);
        MMA_STEP(0);
        // k2=1: prefetch (ks+1, k2=0) into buf0 (stage ks+1 is resident), compute buf1
        if (ks + 1 < NCHUNKS){
            const uint32_t stn = (uint32_t)(((ks + 1) & 3) * STAGEB);
            LOAD_FRAGS(0, aOff + stn, bOff + stn);
        }
        MMA_STEP(1);
    }
    #undef ISSUE
    #undef LOAD_FRAGS
    #undef MMA_STEP

    // ---- epilogue: d2 = f2 + m2 - 2*dot, min-reduce ----
    {
        const int q = lane >> 2;        // row-in-8 group
        const int ql = lane & 3;        // col pair selector
        float m2v[4][2], f2lo[4], f2hi[4];
        #pragma unroll
        for (int ni = 0; ni < 4; ni++){
            int c = warpN*32 + ni*8 + 2*ql;
            m2v[ni][0] = m2s[c];
            m2v[ni][1] = m2s[c + 1];
        }
        #pragma unroll
        for (int mi = 0; mi < 4; mi++){
            f2lo[mi] = f2s[warpM*64 + mi*16 + q];
            f2hi[mi] = f2s[warpM*64 + mi*16 + q + 8];
        }
        #pragma unroll
        for (int mi = 0; mi < 4; mi++){
            float vlo = __int_as_float(0x7F800000);
            float vhi = vlo;
            #pragma unroll
            for (int ni = 0; ni < 4; ni++){
                vlo = fminf(vlo, fminf(fmaf(-2.f, acc[mi][ni][0], f2lo[mi] + m2v[ni][0]),
                                       fmaf(-2.f, acc[mi][ni][1], f2lo[mi] + m2v[ni][1])));
                vhi = fminf(vhi, fminf(fmaf(-2.f, acc[mi][ni][2], f2hi[mi] + m2v[ni][0]),
                                       fmaf(-2.f, acc[mi][ni][3], f2hi[mi] + m2v[ni][1])));
            }
            #pragma unroll
            for (int o = 1; o < 4; o <<= 1){
                vlo = fminf(vlo, __shfl_xor_sync(0xFFFFFFFFu, vlo, o));
                vhi = fminf(vhi, __shfl_xor_sync(0xFFFFFFFFu, vhi, o));
            }
            if (ql == 0){
                int r = warpM*64 + mi*16 + q;
                atomicMin(&sred[r],     __float_as_uint(fmaxf(vlo, 0.f)));
                atomicMin(&sred[r + 8], __float_as_uint(fmaxf(vhi, 0.f)));
            }
        }
    }
    __syncthreads();
    if (tid < 128)
        atomicMin(&g_minbits[rowBase + tid], sred[tid]);
}

// ---------------------------------------------------------------------------
__global__ void k_scores(float* __restrict__ out){
    __shared__ unsigned int red[256];
    const int b = blockIdx.x;
    unsigned int mb = 0u;
    for (int i = threadIdx.x; i < FHW*FHW; i += 256)
        mb = max(mb, g_minbits[b*FHW*FHW + i]);
    red[threadIdx.x] = mb; __syncthreads();
    for (int s = 128; s > 0; s >>= 1){
        if (threadIdx.x < s) red[threadIdx.x] = max(red[threadIdx.x], red[threadIdx.x + s]);
        __syncthreads();
    }
    if (threadIdx.x == 0) out[b] = sqrtf(__uint_as_float(red[0]));
}

__global__ void k_resize(){
    int idx = blockIdx.x * blockDim.x + threadIdx.x;
    if (idx >= NPIX) return;
    int x = idx % IMG, y = (idx / IMG) % IMG, b = idx / (IMG*IMG);
    float fy = y * 0.125f - 0.4375f;
    float fx = x * 0.125f - 0.4375f;
    float fy0 = floorf(fy), fx0 = floorf(fx);
    float wy = fy - fy0, wx = fx - fx0;
    int y0 = max((int)fy0, 0), y1 = min((int)fy0 + 1, FHW-1);
    int x0 = max((int)fx0, 0), x1 = min((int)fx0 + 1, FHW-1);
    const unsigned int* mb = g_minbits + b*FHW*FHW;
    float s00 = sqrtf(__uint_as_float(mb[y0*FHW + x0]));
    float s01 = sqrtf(__uint_as_float(mb[y0*FHW + x1]));
    float s10 = sqrtf(__uint_as_float(mb[y1*FHW + x0]));
    float s11 = sqrtf(__uint_as_float(mb[y1*FHW + x1]));
    g_resized[idx] = (1.f-wy)*((1.f-wx)*s00 + wx*s01) + wy*((1.f-wx)*s10 + wx*s11);
}

__global__ void k_blurh(){
    __shared__ float w[17];
    if (threadIdx.x < 17) w[threadIdx.x] = g_gauss[threadIdx.x];
    __syncthreads();
    int idx = blockIdx.x * blockDim.x + threadIdx.x;
    if (idx >= NPIX) return;
    int x = idx % IMG, y = (idx / IMG) % IMG, b = idx / (IMG*IMG);
    const float* img = g_resized + b*IMG*IMG;
    float s = 0.f;
    #pragma unroll
    for (int t = 0; t < 17; t++){
        int yy = y - 8 + t;
        yy = (yy < 0) ? -yy : yy;
        yy = (yy > IMG-1) ? 2*(IMG-1) - yy : yy;
        s += w[t] * img[yy*IMG + x];
    }
    g_tmpb[idx] = s;
}

__global__ void k_blurv(float* __restrict__ out){
    __shared__ float w[17];
    if (threadIdx.x < 17) w[threadIdx.x] = g_gauss[threadIdx.x];
    __syncthreads();
    int idx = blockIdx.x * blockDim.x + threadIdx.x;
    if (idx >= NPIX) return;
    int x = idx % IMG, y = (idx / IMG) % IMG, b = idx / (IMG*IMG);
    const float* img = g_tmpb + b*IMG*IMG;
    float s = 0.f;
    #pragma unroll
    for (int t = 0; t < 17; t++){
        int xx = x - 8 + t;
        xx = (xx < 0) ? -xx : xx;
        xx = (xx > IMG-1) ? 2*(IMG-1) - xx : xx;
        s += w[t] * img[y*IMG + xx];
    }
    out[BIMG + idx] = s;
}

// ---------------------------------------------------------------------------
extern "C" void kernel_launch(void* const* d_in, const int* in_sizes, int n_in,
                              void* d_out, int out_size){
    const float* feat = (const float*)d_in[0];
    const float* mem  = (const float*)d_in[1];
    if (n_in >= 2 && in_sizes[0] == MMEM * CDIM){
        const float* t = feat; feat = mem; mem = t;
    }
    float* out = (float*)d_out;

    cudaFuncSetAttribute(k_gemm_tc, cudaFuncAttributeMaxDynamicSharedMemorySize, SMEM_TOTAL);

    k_init<<<(NFEAT + 255)/256, 256>>>();
    k_prep<<<NFEAT/8, 256>>>(feat, NFEAT, NFEAT, 0);
    k_prep<<<MPAD2/8, 256>>>(mem, MPAD2, MMEM, 1);

    dim3 g(NFEAT/MTILE, NTILES);   // 49 x 391, x fastest -> B tile L2 reuse
    k_gemm_tc<<<g, 256, SMEM_TOTAL>>>();

    k_scores<<<BIMG, 256>>>(out);
    int pb = (NPIX + 255)/256;
    k_resize<<<pb, 256>>>();
    k_blurh<<<pb, 256>>>();
    k_blurv<<<pb, 256>>>(out);
}